// round 15
// baseline (speedup 1.0000x reference)
#include <cuda_runtime.h>
#include <cstdint>

#define NU_MAX 50000
#define NI_MAX 50000
#define E_MAX  100000

// ---------------- device scratch (static; no allocations allowed) ----------
__device__ float g_v_u[NU_MAX * 512];     // V projection, user
__device__ float g_v_i[NI_MAX * 512];     // V projection, item
__device__ float g_aqk_u[NU_MAX * 16];    // per node: [0..7]=aq, [8..15]=ak
__device__ float g_aqk_i[NI_MAX * 16];
__device__ uint32_t g_xc_u[NU_MAX * 256]; // tf32(RNA)-converted X, user
__device__ uint32_t g_xc_i[NI_MAX * 256]; // tf32(RNA)-converted X, item
__device__ uint32_t g_wc_u[512 * 256];    // tf32(RNA)-converted Wv_user
__device__ uint32_t g_wc_i[512 * 256];    // tf32(RNA)-converted Wv_item
__device__ float g_A_u[16 * 256];         // effective attn proj: rows 0..7 q, 8..15 k
__device__ float g_A_i[16 * 256];
__device__ float g_beff_u[16];
__device__ float g_beff_i[16];
// zeroed block: den [0, 3*NU*8) | cnt [3*NU*8, 3*NU*9) | fill [3*NU*9, 3*NU*10)
__device__ float g_zero[3 * NU_MAX * 10];
__device__ int   g_off[3 * NU_MAX];       // CSR exclusive offsets
__device__ int   g_csr[3 * E_MAX];        // edge ids grouped by dst
__device__ float g_edge[3 * E_MAX * 8];   // exp(score)

#define DEN_BASE  (g_zero)
#define CNT_BASE  ((int*)(g_zero + 3 * NU_MAX * 8))
#define FILL_BASE ((int*)(g_zero + 3 * NU_MAX * 9))

struct EP {
    const int* src; const int* dst;
    const float* aqk_s; const float* aqk_d;
    const float* v_s; float* outp;
    int E; int pad;
};
struct EP3 { EP e[3]; };

// ---------------- helpers ----------------
__device__ __forceinline__ uint32_t to_tf32(float f) {
    uint32_t r;
    asm("cvt.rna.tf32.f32 %0, %1;" : "=r"(r) : "f"(f));
    return r;
}
__device__ __forceinline__ void mma_tf32(float* c, uint32_t a0, uint32_t a1,
                                         uint32_t a2, uint32_t a3,
                                         uint32_t b0, uint32_t b1) {
    asm("mma.sync.aligned.m16n8k8.row.col.f32.tf32.tf32.f32 "
        "{%0,%1,%2,%3}, {%4,%5,%6,%7}, {%8,%9}, {%0,%1,%2,%3};"
        : "+f"(c[0]), "+f"(c[1]), "+f"(c[2]), "+f"(c[3])
        : "r"(a0), "r"(a1), "r"(a2), "r"(a3), "r"(b0), "r"(b1));
}
__device__ __forceinline__ void cp16(uint32_t smem_dst, const void* gsrc) {
    asm volatile("cp.async.cg.shared.global [%0], [%1], 16;"
                 :: "r"(smem_dst), "l"(gsrc) : "memory");
}

// ---------------- prep: fold wa into Wq/Wk -> effective [16,256] matrices ---
__global__ void prep_kernel(const float* __restrict__ Wq_u, const float* __restrict__ bq_u,
                            const float* __restrict__ Wk_u, const float* __restrict__ bk_u,
                            const float* __restrict__ Wq_i, const float* __restrict__ bq_i,
                            const float* __restrict__ Wk_i, const float* __restrict__ bk_i,
                            const float* __restrict__ wa_u, const float* __restrict__ wa_i) {
    int b = blockIdx.x;  // 0:Wq_u 1:Wk_u 2:Wq_i 3:Wk_i
    const float* W    = (b == 0) ? Wq_u : (b == 1) ? Wk_u : (b == 2) ? Wq_i : Wk_i;
    const float* bias = (b == 0) ? bq_u : (b == 1) ? bk_u : (b == 2) ? bq_i : bk_i;
    const float* wa   = (b < 2) ? wa_u : wa_i;
    float* A  = (b < 2) ? g_A_u : g_A_i;
    float* be = (b < 2) ? g_beff_u : g_beff_i;
    int rowoff = (b & 1) * 8;
    int k = threadIdx.x;
    __shared__ float was[64];
    if (k < 64) was[k] = wa[k];
    __syncthreads();
#pragma unroll
    for (int h = 0; h < 8; h++) {
        float s = 0.f;
        for (int d = 0; d < 64; d++) s += W[(h * 64 + d) * 256 + k] * was[d];
        A[(rowoff + h) * 256 + k] = s;
    }
    if (k < 8) {
        float s = 0.f;
        for (int d = 0; d < 64; d++) s += bias[k * 64 + d] * was[d];
        be[rowoff + k] = s;
    }
}

// ---------------- Wv -> tf32 conversion (RNA, same numerics as before) ------
__global__ void wconv_kernel(const float* __restrict__ Wv_u,
                             const float* __restrict__ Wv_i) {
    int i = blockIdx.x * blockDim.x + threadIdx.x;  // 512*256 total
    g_wc_u[i] = to_tf32(Wv_u[i]);
    g_wc_i[i] = to_tf32(Wv_i[i]);
}

// ---------------- attn projections + X -> tf32 copy -------------------------
__global__ void __launch_bounds__(256) attnproj_kernel(const float* __restrict__ X,
                                                       int isUser, int N) {
    const float* A  = isUser ? g_A_u : g_A_i;
    const float* be = isUser ? g_beff_u : g_beff_i;
    float* outp     = isUser ? g_aqk_u : g_aqk_i;
    uint32_t* xc    = isUser ? g_xc_u : g_xc_i;

    __shared__ __align__(16) float xs[16][260];
    __shared__ __align__(16) float as[16][260];
    int tid = threadIdx.x;
    int nb = blockIdx.x * 16;

#pragma unroll
    for (int i = 0; i < 4; i++) {
        int idx = i * 256 + tid;
        int r = idx >> 6, k4 = idx & 63;
        int gr = nb + r; if (gr >= N) gr = N - 1;
        float4 v = *(const float4*)(X + (size_t)gr * 256 + k4 * 4);
        *(float4*)&xs[r][k4 * 4] = v;
        if (nb + r < N) {
            uint4 c;
            c.x = to_tf32(v.x); c.y = to_tf32(v.y);
            c.z = to_tf32(v.z); c.w = to_tf32(v.w);
            *(uint4*)(xc + (size_t)(nb + r) * 256 + k4 * 4) = c;
        }
    }
#pragma unroll
    for (int i = 0; i < 4; i++) {
        int idx = i * 256 + tid;
        int r = idx >> 6, k4 = idx & 63;
        *(float4*)&as[r][k4 * 4] = *(const float4*)(A + r * 256 + k4 * 4);
    }
    __syncthreads();

    int n = tid >> 4, j = tid & 15;
    float4 acc = make_float4(0.f, 0.f, 0.f, 0.f);
#pragma unroll 16
    for (int k4 = 0; k4 < 64; k4++) {
        float4 xv = *(const float4*)&xs[n][k4 * 4];
        float4 av = *(const float4*)&as[j][k4 * 4];
        acc.x = fmaf(xv.x, av.x, acc.x);
        acc.y = fmaf(xv.y, av.y, acc.y);
        acc.z = fmaf(xv.z, av.z, acc.z);
        acc.w = fmaf(xv.w, av.w, acc.w);
    }
    if (nb + n < N)
        outp[(size_t)(nb + n) * 16 + j] = (acc.x + acc.y) + (acc.z + acc.w) + be[j];
}

// ---------------- V GEMM: cp.async + register-pipelined mma.sync tf32 -------
// CTA tile 128(m) x 64(n); 2-stage smem pipeline; B-fragments prefetched one
// kk ahead so LDS latency overlaps MMA issue.
__global__ void __launch_bounds__(256) gemm_cp_kernel(const uint32_t* __restrict__ Xc,
                                                      const uint32_t* __restrict__ Wc,
                                                      const float* __restrict__ bias,
                                                      int isUser, int M) {
    float* C = isUser ? g_v_u : g_v_i;
    __shared__ uint32_t As[2][128][36];
    __shared__ uint32_t Bs[2][64][36];
    __shared__ float s_bias[64];

    int tid = threadIdx.x, lane = tid & 31, warp = tid >> 5;
    int wm = (warp & 3) * 32;
    int wn = (warp >> 2) * 32;
    int n0 = blockIdx.x * 64;
    int m0 = blockIdx.y * 128;
    int lq = lane >> 2;
    int lr = lane & 3;

    if (tid < 64) s_bias[tid] = bias[n0 + tid];

    int arow = tid >> 1, acol = (tid & 1) * 16;
    int gr = m0 + arow; if (gr >= M) gr = M - 1;
    const uint32_t* a_src = Xc + (size_t)gr * 256 + acol;
    uint32_t a_dst[2];
    a_dst[0] = (uint32_t)__cvta_generic_to_shared(&As[0][arow][acol]);
    a_dst[1] = (uint32_t)__cvta_generic_to_shared(&As[1][arow][acol]);
    int brow = tid >> 2, bcol = (tid & 3) * 8;
    const uint32_t* b_src = Wc + (size_t)(n0 + brow) * 256 + bcol;
    uint32_t b_dst[2];
    b_dst[0] = (uint32_t)__cvta_generic_to_shared(&Bs[0][brow][bcol]);
    b_dst[1] = (uint32_t)__cvta_generic_to_shared(&Bs[1][brow][bcol]);

    float acc[2][4][4];
#pragma unroll
    for (int mt = 0; mt < 2; mt++)
#pragma unroll
        for (int nt = 0; nt < 4; nt++)
#pragma unroll
            for (int i = 0; i < 4; i++) acc[mt][nt][i] = 0.f;

#define ISSUE(c, buf) do { \
        const uint32_t* _as = a_src + (c) * 32; \
        const uint32_t* _bs = b_src + (c) * 32; \
        cp16(a_dst[buf] + 0,  _as + 0); \
        cp16(a_dst[buf] + 16, _as + 4); \
        cp16(a_dst[buf] + 32, _as + 8); \
        cp16(a_dst[buf] + 48, _as + 12); \
        cp16(b_dst[buf] + 0,  _bs + 0); \
        cp16(b_dst[buf] + 16, _bs + 4); \
        asm volatile("cp.async.commit_group;" ::: "memory"); \
    } while (0)

    ISSUE(0, 0);
    ISSUE(1, 1);

#pragma unroll
    for (int c = 0; c < 8; c++) {
        if (c < 7) asm volatile("cp.async.wait_group 1;" ::: "memory");
        else       asm volatile("cp.async.wait_group 0;" ::: "memory");
        __syncthreads();
        int bf = c & 1;
        // prefetch kk=0 B-fragments
        uint32_t bcur[4][2];
#pragma unroll
        for (int nt = 0; nt < 4; nt++) {
            int n = wn + nt * 8 + lq;
            bcur[nt][0] = Bs[bf][n][lr];
            bcur[nt][1] = Bs[bf][n][lr + 4];
        }
#pragma unroll
        for (int kk = 0; kk < 4; kk++) {
            int k0 = kk * 8;
            uint32_t bnx[4][2];
            if (kk < 3) {
#pragma unroll
                for (int nt = 0; nt < 4; nt++) {
                    int n = wn + nt * 8 + lq;
                    bnx[nt][0] = Bs[bf][n][k0 + 8 + lr];
                    bnx[nt][1] = Bs[bf][n][k0 + 8 + lr + 4];
                }
            }
#pragma unroll
            for (int mt = 0; mt < 2; mt++) {
                int r0 = wm + mt * 16 + lq;
                uint32_t a0 = As[bf][r0][k0 + lr];
                uint32_t a1 = As[bf][r0 + 8][k0 + lr];
                uint32_t a2 = As[bf][r0][k0 + lr + 4];
                uint32_t a3 = As[bf][r0 + 8][k0 + lr + 4];
#pragma unroll
                for (int nt = 0; nt < 4; nt++)
                    mma_tf32(acc[mt][nt], a0, a1, a2, a3, bcur[nt][0], bcur[nt][1]);
            }
            if (kk < 3) {
#pragma unroll
                for (int nt = 0; nt < 4; nt++) {
                    bcur[nt][0] = bnx[nt][0];
                    bcur[nt][1] = bnx[nt][1];
                }
            }
        }
        __syncthreads();
        if (c + 2 < 8) ISSUE(c + 2, bf);
    }
#undef ISSUE

#pragma unroll
    for (int mt = 0; mt < 2; mt++) {
        int row = m0 + wm + mt * 16 + lq;
#pragma unroll
        for (int nt = 0; nt < 4; nt++) {
            int cl = wn + nt * 8 + 2 * lr;
            float bx = s_bias[cl], by = s_bias[cl + 1];
            if (row < M) {
                float2 o = make_float2(acc[mt][nt][0] + bx, acc[mt][nt][1] + by);
                *(float2*)(C + (size_t)row * 512 + n0 + cl) = o;
            }
            if (row + 8 < M) {
                float2 o = make_float2(acc[mt][nt][2] + bx, acc[mt][nt][3] + by);
                *(float2*)(C + (size_t)(row + 8) * 512 + n0 + cl) = o;
            }
        }
    }
}

// ---------------- edge phase ------------------------------------------------
// Scores are sums of small projections, so softmax without max-subtraction is
// numerically safe and analytically identical (exp(max) cancels).
__global__ void score_all(EP3 P) {
    int et = blockIdx.y;
    EP p = P.e[et];
    int e = blockIdx.x * blockDim.x + threadIdx.x;
    if (e >= p.E) return;
    int s = p.src[e], d = p.dst[e];
    float* den = DEN_BASE + (size_t)et * NU_MAX * 8;
    int* cnt = CNT_BASE + (size_t)et * NU_MAX;
    float* edge = g_edge + (size_t)et * E_MAX * 8;
    float4 ak0 = *(const float4*)(p.aqk_s + s * 16 + 8);
    float4 ak1 = *(const float4*)(p.aqk_s + s * 16 + 12);
    float4 aq0 = *(const float4*)(p.aqk_d + d * 16);
    float4 aq1 = *(const float4*)(p.aqk_d + d * 16 + 4);
    float ex[8];
    ex[0] = __expf((ak0.x + aq0.x) * 0.125f);
    ex[1] = __expf((ak0.y + aq0.y) * 0.125f);
    ex[2] = __expf((ak0.z + aq0.z) * 0.125f);
    ex[3] = __expf((ak0.w + aq0.w) * 0.125f);
    ex[4] = __expf((ak1.x + aq1.x) * 0.125f);
    ex[5] = __expf((ak1.y + aq1.y) * 0.125f);
    ex[6] = __expf((ak1.z + aq1.z) * 0.125f);
    ex[7] = __expf((ak1.w + aq1.w) * 0.125f);
    *(float4*)(edge + e * 8)     = make_float4(ex[0], ex[1], ex[2], ex[3]);
    *(float4*)(edge + e * 8 + 4) = make_float4(ex[4], ex[5], ex[6], ex[7]);
#pragma unroll
    for (int h = 0; h < 8; h++) atomicAdd(&den[d * 8 + h], ex[h]);
    atomicAdd(&cnt[d], 1);
}

// exclusive scan of cnt per etype -> g_off. One 1024-thread block per etype.
__global__ void __launch_bounds__(1024) scan_all(int NUr, int NIr) {
    int et = blockIdx.x;
    int Nd = (et == 0) ? NIr : NUr;
    const int* cnt = CNT_BASE + (size_t)et * NU_MAX;
    int* off = g_off + (size_t)et * NU_MAX;
    int tid = threadIdx.x;
    int chunk = (Nd + 1023) >> 10;
    int s0 = tid * chunk, s1 = s0 + chunk;
    if (s1 > Nd) s1 = Nd;
    int s = 0;
    for (int i = s0; i < s1; i++) s += cnt[i];
    __shared__ int sh[1024];
    sh[tid] = s;
    __syncthreads();
    for (int o = 1; o < 1024; o <<= 1) {
        int add = (tid >= o) ? sh[tid - o] : 0;
        __syncthreads();
        sh[tid] += add;
        __syncthreads();
    }
    int run = sh[tid] - s;  // exclusive prefix of this chunk
    for (int i = s0; i < s1; i++) { off[i] = run; run += cnt[i]; }
}

// scatter edge ids into CSR slots
__global__ void fill_all(EP3 P) {
    int et = blockIdx.y;
    EP p = P.e[et];
    int e = blockIdx.x * blockDim.x + threadIdx.x;
    if (e >= p.E) return;
    int d = p.dst[e];
    int pos = g_off[(size_t)et * NU_MAX + d] +
              atomicAdd(&FILL_BASE[(size_t)et * NU_MAX + d], 1);
    g_csr[(size_t)et * E_MAX + pos] = e;
}

// den[d,h] <- 1 / (den[d,h] * max(cnt[d],1))
__global__ void norm_all(int NUr, int NIr) {
    int et = blockIdx.y;
    int i = blockIdx.x * blockDim.x + threadIdx.x;
    int Nd = (et == 0) ? NIr : NUr;
    if (i >= Nd * 8) return;
    float* den = DEN_BASE + (size_t)et * NU_MAX * 8;
    float dc = (float)max(CNT_BASE[(size_t)et * NU_MAX + (i >> 3)], 1);
    den[i] = 1.0f / (den[i] * dc);
}

// ---------------- gather: one block per dst node, MLP-batched loads ---------
__device__ __forceinline__ void gather_seg(float4& acc, int base, int n,
                                           const int* __restrict__ csr,
                                           const float* __restrict__ edge,
                                           const int* __restrict__ srcArr,
                                           const float* __restrict__ vtab,
                                           float w, int h, int t) {
    for (int i = 0; i < n; i += 4) {
        int m = n - i; if (m > 4) m = 4;
        int ee[4], ss[4];
#pragma unroll
        for (int j = 0; j < 4; j++) ee[j] = (j < m) ? csr[base + i + j] : 0;
#pragma unroll
        for (int j = 0; j < 4; j++) ss[j] = (j < m) ? srcArr[ee[j]] : 0;
        float aa[4];
#pragma unroll
        for (int j = 0; j < 4; j++) aa[j] = (j < m) ? edge[(size_t)ee[j] * 8 + h] * w : 0.f;
#pragma unroll
        for (int j = 0; j < 4; j++) {
            if (j < m) {
                float4 v = *(const float4*)(vtab + (size_t)ss[j] * 512 + t * 4);
                acc.x = fmaf(v.x, aa[j], acc.x); acc.y = fmaf(v.y, aa[j], acc.y);
                acc.z = fmaf(v.z, aa[j], acc.z); acc.w = fmaf(v.w, aa[j], acc.w);
            }
        }
    }
}

// item: etype0 (src=user, v_u)
__global__ void __launch_bounds__(128) gather_item(const int* __restrict__ src0,
                                                   float* __restrict__ outp, int NIr) {
    int d = blockIdx.x;
    int t = threadIdx.x, h = t >> 4;
    float w = DEN_BASE[d * 8 + h];
    float4 acc = make_float4(0.f, 0.f, 0.f, 0.f);
    gather_seg(acc, g_off[d], CNT_BASE[d], g_csr, g_edge, src0, g_v_u, w, h, t);
    *(float4*)(outp + (size_t)d * 512 + t * 4) = acc;
}

// user: etype1 (src=item, v_i) + etype2 (src=user, v_u), summed
__global__ void __launch_bounds__(128) gather_user(const int* __restrict__ src1,
                                                   const int* __restrict__ src2,
                                                   float* __restrict__ outp, int NUr) {
    int d = blockIdx.x;
    int t = threadIdx.x, h = t >> 4;
    float4 acc = make_float4(0.f, 0.f, 0.f, 0.f);
    {
        float w = DEN_BASE[(size_t)NU_MAX * 8 + d * 8 + h];
        gather_seg(acc, g_off[NU_MAX + d], CNT_BASE[NU_MAX + d],
                   g_csr + E_MAX, g_edge + (size_t)E_MAX * 8, src1, g_v_i, w, h, t);
    }
    {
        float w = DEN_BASE[(size_t)2 * NU_MAX * 8 + d * 8 + h];
        gather_seg(acc, g_off[2 * NU_MAX + d], CNT_BASE[2 * NU_MAX + d],
                   g_csr + 2 * E_MAX, g_edge + (size_t)2 * E_MAX * 8, src2, g_v_u, w, h, t);
    }
    *(float4*)(outp + (size_t)d * 512 + t * 4) = acc;
}

// ---------------- host ----------------
extern "C" void kernel_launch(void* const* d_in, const int* in_sizes, int n_in,
                              void* d_out, int out_size) {
    const float* x_u  = (const float*)d_in[0];
    const float* x_i  = (const float*)d_in[1];
    const float* Wq_u = (const float*)d_in[2];  const float* bq_u = (const float*)d_in[3];
    const float* Wk_u = (const float*)d_in[4];  const float* bk_u = (const float*)d_in[5];
    const float* Wv_u = (const float*)d_in[6];  const float* bv_u = (const float*)d_in[7];
    const float* Wq_i = (const float*)d_in[8];  const float* bq_i = (const float*)d_in[9];
    const float* Wk_i = (const float*)d_in[10]; const float* bk_i = (const float*)d_in[11];
    const float* Wv_i = (const float*)d_in[12]; const float* bv_i = (const float*)d_in[13];
    const float* wa_u = (const float*)d_in[14]; const float* wa_i = (const float*)d_in[15];
    const int* src_c  = (const int*)d_in[16];   const int* dst_c  = (const int*)d_in[17];
    const int* src_cb = (const int*)d_in[18];   const int* dst_cb = (const int*)d_in[19];
    const int* src_f  = (const int*)d_in[20];   const int* dst_f  = (const int*)d_in[21];

    int NU = in_sizes[0] / 256;
    int NI = in_sizes[1] / 256;
    int E0 = in_sizes[16], E1 = in_sizes[18], E2 = in_sizes[20];
    int Emax = E0 > E1 ? E0 : E1; if (E2 > Emax) Emax = E2;
    int Nmax = NU > NI ? NU : NI;

    float* out_user = (float*)d_out;
    float* out_item = out_user + (size_t)NU * 512;

    void *p_zero, *p_vu, *p_vi, *p_aqku, *p_aqki, *p_xcu, *p_xci, *p_wcu, *p_wci;
    cudaGetSymbolAddress(&p_zero, g_zero);
    cudaGetSymbolAddress(&p_vu, g_v_u);
    cudaGetSymbolAddress(&p_vi, g_v_i);
    cudaGetSymbolAddress(&p_aqku, g_aqk_u);
    cudaGetSymbolAddress(&p_aqki, g_aqk_i);
    cudaGetSymbolAddress(&p_xcu, g_xc_u);
    cudaGetSymbolAddress(&p_xci, g_xc_i);
    cudaGetSymbolAddress(&p_wcu, g_wc_u);
    cudaGetSymbolAddress(&p_wci, g_wc_i);

    cudaMemsetAsync(p_zero, 0, sizeof(float) * 3 * NU_MAX * 10);

    prep_kernel<<<4, 256>>>(Wq_u, bq_u, Wk_u, bk_u, Wq_i, bq_i, Wk_i, bk_i, wa_u, wa_i);
    wconv_kernel<<<512, 256>>>(Wv_u, Wv_i);
    attnproj_kernel<<<(NU + 15) / 16, 256>>>(x_u, 1, NU);
    attnproj_kernel<<<(NI + 15) / 16, 256>>>(x_i, 0, NI);
    gemm_cp_kernel<<<dim3(8, (NU + 127) / 128), 256>>>(
        (const uint32_t*)p_xcu, (const uint32_t*)p_wcu, bv_u, 1, NU);
    gemm_cp_kernel<<<dim3(8, (NI + 127) / 128), 256>>>(
        (const uint32_t*)p_xci, (const uint32_t*)p_wci, bv_i, 0, NI);

    EP3 P;
    // ('user','clicks','item'): src=user, dst=item -> h_item
    P.e[0] = {src_c, dst_c, (const float*)p_aqku, (const float*)p_aqki,
              (const float*)p_vu, out_item, E0, 0};
    // ('item','clicked_by','user'): src=item, dst=user -> h_user
    P.e[1] = {src_cb, dst_cb, (const float*)p_aqki, (const float*)p_aqku,
              (const float*)p_vi, out_user, E1, 0};
    // ('user','follows','user') -> h_user
    P.e[2] = {src_f, dst_f, (const float*)p_aqku, (const float*)p_aqku,
              (const float*)p_vu, out_user, E2, 0};

    dim3 gb((Emax + 255) / 256, 3);
    score_all<<<gb, 256>>>(P);
    scan_all<<<3, 1024>>>(NU, NI);
    fill_all<<<gb, 256>>>(P);
    norm_all<<<dim3((Nmax * 8 + 255) / 256, 3), 256>>>(NU, NI);
    gather_item<<<NI, 128>>>(src_c, out_item, NI);
    gather_user<<<NU, 128>>>(src_cb, src_f, out_user, NU);
}